// round 17
// baseline (speedup 1.0000x reference)
#include <cuda_runtime.h>
#include <cuda_bf16.h>
#include <cstdint>

#define FN   128
#define FE   32
#define MSGW 32
#define QW   192          // Q cols: [0,32)=nf@We0, [32,64)=nf@We1, [64,192)=nf@Wn0
#define MAXN 50000
#define BE   256

__device__ float g_Q[(size_t)MAXN * QW];
__device__ float g_MS[(size_t)MAXN * MSGW];
__device__ int   g_is64;
__device__ __nv_bfloat16 gWhi[128 * 192];
__device__ __nv_bfloat16 gWlo[128 * 192];

// ---------------------------------------------------------------------------
// helpers
// ---------------------------------------------------------------------------
static __device__ __forceinline__ uint32_t sptr(const void* p) {
    return (uint32_t)__cvta_generic_to_shared(p);
}
static __device__ __forceinline__ void ldsm_x4(uint32_t* r, uint32_t a) {
    asm volatile("ldmatrix.sync.aligned.m8n8.x4.shared.b16 {%0,%1,%2,%3},[%4];"
                 : "=r"(r[0]), "=r"(r[1]), "=r"(r[2]), "=r"(r[3]) : "r"(a));
}
static __device__ __forceinline__ void ldsm_x4t(uint32_t* r, uint32_t a) {
    asm volatile("ldmatrix.sync.aligned.m8n8.x4.trans.shared.b16 {%0,%1,%2,%3},[%4];"
                 : "=r"(r[0]), "=r"(r[1]), "=r"(r[2]), "=r"(r[3]) : "r"(a));
}
static __device__ __forceinline__ void mma16816(float* c, const uint32_t* a,
                                                uint32_t b0, uint32_t b1) {
    asm volatile(
        "mma.sync.aligned.m16n8k16.row.col.f32.bf16.bf16.f32 "
        "{%0,%1,%2,%3},{%4,%5,%6,%7},{%8,%9},{%0,%1,%2,%3};"
        : "+f"(c[0]), "+f"(c[1]), "+f"(c[2]), "+f"(c[3])
        : "r"(a[0]), "r"(a[1]), "r"(a[2]), "r"(a[3]), "r"(b0), "r"(b1));
}
#define CP16(dst, src) \
    asm volatile("cp.async.cg.shared.global [%0],[%1],16;" :: "r"(dst), "l"(src))
#define CP_COMMIT() asm volatile("cp.async.commit_group;" ::: "memory")
#define CP_WAIT(n)  asm volatile("cp.async.wait_group %0;" :: "n"(n) : "memory")

static __device__ __forceinline__ __nv_bfloat162 bf2_hi(float a, float b) {
    __nv_bfloat162 h; h.x = __float2bfloat16(a); h.y = __float2bfloat16(b); return h;
}
static __device__ __forceinline__ __nv_bfloat162 bf2_lo(float a, float b,
                                                        __nv_bfloat162 h) {
    __nv_bfloat162 l;
    l.x = __float2bfloat16(a - __bfloat162float(h.x));
    l.y = __float2bfloat16(b - __bfloat162float(h.y));
    return l;
}
static __device__ __forceinline__ uint32_t b2u(__nv_bfloat162 v) {
    uint32_t u; __builtin_memcpy(&u, &v, 4); return u;
}

// ---------------------------------------------------------------------------
// Prep: detect idx dtype, zero g_MS, split fused W into bf16 hi/lo.
// ---------------------------------------------------------------------------
__global__ void k_prep(const unsigned* __restrict__ wds,
                       const float* __restrict__ We,
                       const float* __restrict__ Wn,
                       int E, int N, int zb) {
    int b = blockIdx.x, t = threadIdx.x;
    if (b == 0) {
        __shared__ unsigned red[256];
        int sample = min(16384, E);
        unsigned v = 0;
        for (int i = t; i < sample; i += 256) v |= wds[2 * i + 1];
        red[t] = v;
        __syncthreads();
        for (int s = 128; s > 0; s >>= 1) {
            if (t < s) red[t] |= red[t + s];
            __syncthreads();
        }
        if (t == 0) g_is64 = (red[0] == 0u) ? 1 : 0;
    } else if (b <= zb) {
        int i = (b - 1) * 256 + t;
        if (i < N * MSGW / 4)
            ((float4*)g_MS)[i] = make_float4(0.f, 0.f, 0.f, 0.f);
    } else {
        int id = (b - 1 - zb) * 256 + t;
        if (id < 128 * 192) {
            int k = id / 192, c = id - k * 192;
            float v;
            if (c < 32)      v = We[(size_t)k * MSGW + c];
            else if (c < 64) v = We[(size_t)(FN + k) * MSGW + (c - 32)];
            else             v = Wn[(size_t)k * FN + (c - 64)];
            __nv_bfloat16 h = __float2bfloat16(v);
            gWhi[id] = h;
            gWlo[id] = __float2bfloat16(v - __bfloat162float(h));
        }
    }
}

// ---------------------------------------------------------------------------
// K1 (unchanged): Q = nf @ fusedW, split-bf16 HMMA, cp.async double-buffered.
// ---------------------------------------------------------------------------
#define STG   36864
#define AHI_O 0
#define ALO_O 5120
#define WHI_O 10240
#define WLO_O 23040
#define G1_SMEM (2 * STG)

__global__ __launch_bounds__(256, 2) void k_gemm1(const float* __restrict__ nf,
                                                  int N) {
    extern __shared__ char smem[];
    uint32_t sbase = sptr(smem);
    int t = threadIdx.x;
    int wid = t >> 5, lane = t & 31;
    int m0 = blockIdx.x * 64;
    int warp_m = wid & 1, warp_n = wid >> 1;
    int rbase = warp_m * 32, cbase = warp_n * 48;

    int arow = t >> 2, aq = t & 3;
    bool arowOK = (m0 + arow) < N;
    const float4* aSrc = (const float4*)(nf + (size_t)(m0 + arow) * FN) + aq * 2;
    uint32_t aDstOff = (uint32_t)(arow * 80 + aq * 16);

    uint32_t aOff = (uint32_t)((rbase + (lane & 15)) * 80 + (lane >> 4) * 16);
    uint32_t wRow = (uint32_t)((lane & 7) + 8 * ((lane >> 3) & 1));
    uint32_t wOff = wRow * 400 + (uint32_t)(cbase + 8 * (lane >> 4)) * 2;

    float c[2][6][4];
#pragma unroll
    for (int mt = 0; mt < 2; mt++)
#pragma unroll
        for (int nt = 0; nt < 6; nt++)
#pragma unroll
            for (int i = 0; i < 4; i++) c[mt][nt][i] = 0.f;

    float4 pa0 = make_float4(0.f, 0.f, 0.f, 0.f), pa1 = pa0;

    auto writeA = [&](uint32_t stageOff) {
        __nv_bfloat162 h0 = bf2_hi(pa0.x, pa0.y), h1 = bf2_hi(pa0.z, pa0.w);
        __nv_bfloat162 h2 = bf2_hi(pa1.x, pa1.y), h3 = bf2_hi(pa1.z, pa1.w);
        uint4 H = make_uint4(b2u(h0), b2u(h1), b2u(h2), b2u(h3));
        uint4 L = make_uint4(b2u(bf2_lo(pa0.x, pa0.y, h0)),
                             b2u(bf2_lo(pa0.z, pa0.w, h1)),
                             b2u(bf2_lo(pa1.x, pa1.y, h2)),
                             b2u(bf2_lo(pa1.z, pa1.w, h3)));
        *(uint4*)(smem + AHI_O + stageOff + aDstOff) = H;
        *(uint4*)(smem + ALO_O + stageOff + aDstOff) = L;
    };
    auto issueW = [&](int kc, uint32_t stageOff) {
#pragma unroll
        for (int j = 0; j < 3; j++) {
            int u = t + 256 * j;
            int wr = u / 24, cq = u - wr * 24;
            CP16(sbase + WHI_O + stageOff + wr * 400 + cq * 16,
                 gWhi + (kc + wr) * 192 + cq * 8);
            CP16(sbase + WLO_O + stageOff + wr * 400 + cq * 16,
                 gWlo + (kc + wr) * 192 + cq * 8);
        }
        CP_COMMIT();
    };

    if (arowOK) { pa0 = aSrc[0]; pa1 = aSrc[1]; }
    issueW(0, 0);
    writeA(0);
    if (arowOK) { pa0 = aSrc[8]; pa1 = aSrc[9]; }
    issueW(32, STG);

#pragma unroll
    for (int ch = 0; ch < 4; ch++) {
        uint32_t stage = (uint32_t)(ch & 1) * STG;
        if (ch < 3) CP_WAIT(1); else CP_WAIT(0);
        __syncthreads();

        uint32_t aHiB = sbase + AHI_O + stage + aOff;
        uint32_t aLoB = sbase + ALO_O + stage + aOff;
        uint32_t wHiB = sbase + WHI_O + stage + wOff;
        uint32_t wLoB = sbase + WLO_O + stage + wOff;
#pragma unroll
        for (int ks = 0; ks < 2; ks++) {
            uint32_t ah[2][4], al[2][4];
            ldsm_x4(ah[0], aHiB + ks * 32);
            ldsm_x4(ah[1], aHiB + ks * 32 + 1280);
            ldsm_x4(al[0], aLoB + ks * 32);
            ldsm_x4(al[1], aLoB + ks * 32 + 1280);
#pragma unroll
            for (int j = 0; j < 3; j++) {
                uint32_t bh[4], bl[4];
                ldsm_x4t(bh, wHiB + ks * 6400 + j * 32);
                ldsm_x4t(bl, wLoB + ks * 6400 + j * 32);
#pragma unroll
                for (int mt = 0; mt < 2; mt++) {
                    mma16816(c[mt][2 * j],     ah[mt], bh[0], bh[1]);
                    mma16816(c[mt][2 * j],     al[mt], bh[0], bh[1]);
                    mma16816(c[mt][2 * j],     ah[mt], bl[0], bl[1]);
                    mma16816(c[mt][2 * j + 1], ah[mt], bh[2], bh[3]);
                    mma16816(c[mt][2 * j + 1], al[mt], bh[2], bh[3]);
                    mma16816(c[mt][2 * j + 1], ah[mt], bl[2], bl[3]);
                }
            }
        }
        __syncthreads();

        if (ch < 3) {
            uint32_t nstage = (uint32_t)((ch + 1) & 1) * STG;
            writeA(nstage);
            if (ch < 2) {
                int kc = (ch + 2) * 32;
                if (arowOK) {
                    pa0 = aSrc[kc >> 2];
                    pa1 = aSrc[(kc >> 2) + 1];
                }
                issueW(kc, stage);
            }
        }
    }

    int g = lane >> 2, tg = lane & 3;
#pragma unroll
    for (int mt = 0; mt < 2; mt++)
#pragma unroll
        for (int nt = 0; nt < 6; nt++) {
            int row = m0 + rbase + 16 * mt + g;
            int col = cbase + 8 * nt + 2 * tg;
            if (row < N)
                *(float2*)&g_Q[(size_t)row * QW + col] =
                    make_float2(c[mt][nt][0], c[mt][nt][1]);
            if (row + 8 < N)
                *(float2*)&g_Q[(size_t)(row + 8) * QW + col] =
                    make_float2(c[mt][nt][2], c[mt][nt][3]);
        }
}

// ---------------------------------------------------------------------------
// K2 v8: gathers software-pipelined across phase A.
//  wave-0 gather LDGs issued BEFORE the HMMA phase; wave-1 issued before
//  wave-0's combine. launch_bounds(256,2) for register headroom.
// ---------------------------------------------------------------------------
__global__ __launch_bounds__(256, 2) void k_edges(const void* __restrict__ idx,
                                                  const float* __restrict__ ef,
                                                  const float* __restrict__ We,
                                                  const float* __restrict__ be,
                                                  int E) {
    __shared__ char sEdge[40960];            // ef hi/lo, later msg (36864B)
    __shared__ __nv_bfloat16 sW2Hi[32 * 40];
    __shared__ __nv_bfloat16 sW2Lo[32 * 40];
    __shared__ int   sN0[BE], sN1[BE];
    __shared__ float sBe[32];

    __nv_bfloat16* sEfHi = (__nv_bfloat16*)sEdge;     // [256][40]
    __nv_bfloat16* sEfLo = sEfHi + 256 * 40;
    float* sMsg = (float*)sEdge;                       // [256][36]

    int t  = threadIdx.x;
    int e0 = blockIdx.x * BE;
    int is64 = g_is64;

    {
        int e = e0 + t;
        if (e < E) {
            if (is64) {
                const long long* pp = (const long long*)idx;
                sN0[t] = (int)pp[e];
                sN1[t] = (int)pp[(size_t)E + e];
            } else {
                const int* pp = (const int*)idx;
                sN0[t] = pp[e];
                sN1[t] = pp[(size_t)E + e];
            }
        } else { sN0[t] = -1; sN1[t] = 0; }
    }
#pragma unroll
    for (int id = t; id < 32 * 32; id += 256) {
        int k = id >> 5, c2 = id & 31;
        float v = We[(size_t)(2 * FN + k) * MSGW + c2];
        __nv_bfloat16 h = __float2bfloat16(v);
        sW2Hi[k * 40 + c2] = h;
        sW2Lo[k * 40 + c2] = __float2bfloat16(v - __bfloat162float(h));
    }
    if (t < 32) sBe[t] = be[t];
    {
        int e = e0 + t;
#pragma unroll
        for (int j = 0; j < 8; j++) {
            float4 v = (e < E) ? ((const float4*)ef)[(size_t)e * 8 + j]
                               : make_float4(0.f, 0.f, 0.f, 0.f);
            __nv_bfloat162 h0 = bf2_hi(v.x, v.y), h1 = bf2_hi(v.z, v.w);
            *(__nv_bfloat162*)&sEfHi[t * 40 + 4 * j]     = h0;
            *(__nv_bfloat162*)&sEfHi[t * 40 + 4 * j + 2] = h1;
            *(__nv_bfloat162*)&sEfLo[t * 40 + 4 * j]     = bf2_lo(v.x, v.y, h0);
            *(__nv_bfloat162*)&sEfLo[t * 40 + 4 * j + 2] = bf2_lo(v.z, v.w, h1);
        }
    }
    __syncthreads();   // sN0/sN1 + ef tiles ready

    // ---- prefetch wave 0 gathers (overlap with phase A HMMA) ----
    int sub = t & 7, mBase = t >> 3;
    int    n0v[4];
    float4 q0v[4], q1v[4];
#pragma unroll
    for (int p = 0; p < 4; p++) {
        int m  = p * 32 + mBase;
        int n0 = sN0[m], n1 = sN1[m];
        n0v[p] = n0;
        int a0 = (n0 < 0) ? 0 : n0;
        int a1 = (n0 < 0) ? 0 : n1;
        q0v[p] = ((const float4*)&g_Q[(size_t)a0 * QW])[sub];
        q1v[p] = ((const float4*)&g_Q[(size_t)a1 * QW + 32])[sub];
    }

    // ---- phase A: HMMA ----
    int wid = t >> 5, lane = t & 31;
    uint32_t aOff = (uint32_t)((wid * 32 + (lane & 15)) * 80 + (lane >> 4) * 16);
    uint32_t aHiB = sptr(sEfHi) + aOff;
    uint32_t aLoB = sptr(sEfLo) + aOff;
    uint32_t wRow = (uint32_t)((lane & 7) + 8 * ((lane >> 3) & 1));
    uint32_t wOff = wRow * 80 + (uint32_t)(8 * (lane >> 4)) * 2;
    uint32_t wHiB = sptr(sW2Hi) + wOff;
    uint32_t wLoB = sptr(sW2Lo) + wOff;

    float c[2][4][4];
#pragma unroll
    for (int mt = 0; mt < 2; mt++)
#pragma unroll
        for (int nt = 0; nt < 4; nt++)
#pragma unroll
            for (int i = 0; i < 4; i++) c[mt][nt][i] = 0.f;

#pragma unroll
    for (int ks = 0; ks < 2; ks++) {
        uint32_t ah[2][4], al[2][4];
        ldsm_x4(ah[0], aHiB + ks * 32);
        ldsm_x4(ah[1], aHiB + ks * 32 + 1280);
        ldsm_x4(al[0], aLoB + ks * 32);
        ldsm_x4(al[1], aLoB + ks * 32 + 1280);
#pragma unroll
        for (int j = 0; j < 2; j++) {
            uint32_t bh[4], bl[4];
            ldsm_x4t(bh, wHiB + ks * 1280 + j * 32);
            ldsm_x4t(bl, wLoB + ks * 1280 + j * 32);
#pragma unroll
            for (int mt = 0; mt < 2; mt++) {
                mma16816(c[mt][2 * j],     ah[mt], bh[0], bh[1]);
                mma16816(c[mt][2 * j],     al[mt], bh[0], bh[1]);
                mma16816(c[mt][2 * j],     ah[mt], bl[0], bl[1]);
                mma16816(c[mt][2 * j + 1], ah[mt], bh[2], bh[3]);
                mma16816(c[mt][2 * j + 1], al[mt], bh[2], bh[3]);
                mma16816(c[mt][2 * j + 1], ah[mt], bl[2], bl[3]);
            }
        }
    }
    __syncthreads();   // ldsm reads done before msg overlays ef

    {
        int g = lane >> 2, tg = lane & 3;
#pragma unroll
        for (int mt = 0; mt < 2; mt++)
#pragma unroll
            for (int nt = 0; nt < 4; nt++) {
                int row = wid * 32 + 16 * mt + g;
                int col = 8 * nt + 2 * tg;
                *(float2*)&sMsg[row * 36 + col] =
                    make_float2(c[mt][nt][0], c[mt][nt][1]);
                *(float2*)&sMsg[(row + 8) * 36 + col] =
                    make_float2(c[mt][nt][2], c[mt][nt][3]);
            }
    }
    __syncthreads();

    // ---- prefetch wave 1, then combine wave 0 ----
    int    n0w[4];
    float4 q0w[4], q1w[4];
#pragma unroll
    for (int p = 0; p < 4; p++) {
        int m  = (4 + p) * 32 + mBase;
        int n0 = sN0[m], n1 = sN1[m];
        n0w[p] = n0;
        int a0 = (n0 < 0) ? 0 : n0;
        int a1 = (n0 < 0) ? 0 : n1;
        q0w[p] = ((const float4*)&g_Q[(size_t)a0 * QW])[sub];
        q1w[p] = ((const float4*)&g_Q[(size_t)a1 * QW + 32])[sub];
    }

    float4 bv = *(const float4*)&sBe[sub * 4];
#pragma unroll
    for (int p = 0; p < 4; p++) {
        if (n0v[p] >= 0) {
            int m = p * 32 + mBase;
            float4 mv = *(const float4*)&sMsg[m * 36 + sub * 4];
            float x0 = fmaxf(mv.x + q0v[p].x + q1v[p].x + bv.x, 0.f);
            float x1 = fmaxf(mv.y + q0v[p].y + q1v[p].y + bv.y, 0.f);
            float x2 = fmaxf(mv.z + q0v[p].z + q1v[p].z + bv.z, 0.f);
            float x3 = fmaxf(mv.w + q0v[p].w + q1v[p].w + bv.w, 0.f);
            float* dst = &g_MS[(size_t)n0v[p] * MSGW + sub * 4];
            asm volatile("red.global.add.v4.f32 [%0], {%1,%2,%3,%4};"
                         :: "l"(dst), "f"(x0), "f"(x1), "f"(x2), "f"(x3)
                         : "memory");
        }
    }
#pragma unroll
    for (int p = 0; p < 4; p++) {
        if (n0w[p] >= 0) {
            int m = (4 + p) * 32 + mBase;
            float4 mv = *(const float4*)&sMsg[m * 36 + sub * 4];
            float x0 = fmaxf(mv.x + q0w[p].x + q1w[p].x + bv.x, 0.f);
            float x1 = fmaxf(mv.y + q0w[p].y + q1w[p].y + bv.y, 0.f);
            float x2 = fmaxf(mv.z + q0w[p].z + q1w[p].z + bv.z, 0.f);
            float x3 = fmaxf(mv.w + q0w[p].w + q1w[p].w + bv.w, 0.f);
            float* dst = &g_MS[(size_t)n0w[p] * MSGW + sub * 4];
            asm volatile("red.global.add.v4.f32 [%0], {%1,%2,%3,%4};"
                         :: "l"(dst), "f"(x0), "f"(x1), "f"(x2), "f"(x3)
                         : "memory");
        }
    }
}

// ---------------------------------------------------------------------------
// K3 (unchanged): out = relu(Q[:,64:192] + MS@Wn1 + bn).
// ---------------------------------------------------------------------------
__global__ __launch_bounds__(256, 4) void k_nodes(const float* __restrict__ Wn,
                                                  const float* __restrict__ bn,
                                                  float* __restrict__ out,
                                                  int N) {
    __shared__ __nv_bfloat16 sMSHi[64 * 40];
    __shared__ __nv_bfloat16 sMSLo[64 * 40];
    __shared__ __nv_bfloat16 sW1Hi[32 * 136];
    __shared__ __nv_bfloat16 sW1Lo[32 * 136];
    __shared__ float sBn[128];

    int t  = threadIdx.x;
    int m0 = blockIdx.x * 64;
    int wid = t >> 5, lane = t & 31;
    int warp_m = wid & 3, warp_n = wid >> 2;

#pragma unroll
    for (int id = t; id < 32 * 128; id += 256) {
        int k = id >> 7, c2 = id & 127;
        float v = Wn[(size_t)(FN + k) * FN + c2];
        __nv_bfloat16 h = __float2bfloat16(v);
        sW1Hi[k * 136 + c2] = h;
        sW1Lo[k * 136 + c2] = __float2bfloat16(v - __bfloat162float(h));
    }
    {
        int row = t >> 2, c0 = (t & 3) * 8;
        int n = m0 + row;
#pragma unroll
        for (int j = 0; j < 2; j++) {
            float4 v = (n < N)
                ? *(const float4*)&g_MS[(size_t)n * MSGW + c0 + 4 * j]
                : make_float4(0.f, 0.f, 0.f, 0.f);
            __nv_bfloat162 h0 = bf2_hi(v.x, v.y), h1 = bf2_hi(v.z, v.w);
            *(__nv_bfloat162*)&sMSHi[row * 40 + c0 + 4 * j]     = h0;
            *(__nv_bfloat162*)&sMSHi[row * 40 + c0 + 4 * j + 2] = h1;
            *(__nv_bfloat162*)&sMSLo[row * 40 + c0 + 4 * j]     = bf2_lo(v.x, v.y, h0);
            *(__nv_bfloat162*)&sMSLo[row * 40 + c0 + 4 * j + 2] = bf2_lo(v.z, v.w, h1);
        }
    }
    if (t < 128) sBn[t] = bn[t];
    __syncthreads();

    uint32_t aOff = (uint32_t)((warp_m * 16 + (lane & 15)) * 80 + (lane >> 4) * 16);
    uint32_t aHiB = sptr(sMSHi) + aOff;
    uint32_t aLoB = sptr(sMSLo) + aOff;
    uint32_t wRow = (uint32_t)((lane & 7) + 8 * ((lane >> 3) & 1));
    uint32_t wOff = wRow * 272 + (uint32_t)(warp_n * 64 + 8 * (lane >> 4)) * 2;
    uint32_t wHiB = sptr(sW1Hi) + wOff;
    uint32_t wLoB = sptr(sW1Lo) + wOff;

    float c[8][4];
#pragma unroll
    for (int nt = 0; nt < 8; nt++)
#pragma unroll
        for (int i = 0; i < 4; i++) c[nt][i] = 0.f;

#pragma unroll
    for (int ks = 0; ks < 2; ks++) {
        uint32_t ah[4], al[4];
        ldsm_x4(ah, aHiB + ks * 32);
        ldsm_x4(al, aLoB + ks * 32);
#pragma unroll
        for (int j = 0; j < 4; j++) {
            uint32_t bh[4], bl[4];
            ldsm_x4t(bh, wHiB + ks * 4352 + j * 32);
            ldsm_x4t(bl, wLoB + ks * 4352 + j * 32);
            mma16816(c[2 * j],     ah, bh[0], bh[1]);
            mma16816(c[2 * j],     al, bh[0], bh[1]);
            mma16816(c[2 * j],     ah, bl[0], bl[1]);
            mma16816(c[2 * j + 1], ah, bh[2], bh[3]);
            mma16816(c[2 * j + 1], al, bh[2], bh[3]);
            mma16816(c[2 * j + 1], ah, bl[2], bl[3]);
        }
    }

    int g = lane >> 2, tg = lane & 3;
#pragma unroll
    for (int nt = 0; nt < 8; nt++) {
        int col = warp_n * 64 + 8 * nt + 2 * tg;
        float2 b = *(const float2*)&sBn[col];
#pragma unroll
        for (int half = 0; half < 2; half++) {
            int row = m0 + warp_m * 16 + g + 8 * half;
            if (row < N) {
                float2 q = *(const float2*)&g_Q[(size_t)row * QW + 64 + col];
                float2 o;
                o.x = fmaxf(c[nt][2 * half]     + q.x + b.x, 0.f);
                o.y = fmaxf(c[nt][2 * half + 1] + q.y + b.y, 0.f);
                *(float2*)&out[(size_t)row * FN + col] = o;
            }
        }
    }
}

// ---------------------------------------------------------------------------
extern "C" void kernel_launch(void* const* d_in, const int* in_sizes, int n_in,
                              void* d_out, int out_size) {
    const float* nf  = (const float*)d_in[0];
    const void*  idx = d_in[1];
    const float* ef  = (const float*)d_in[2];
    const float* We  = (const float*)d_in[3];
    const float* be  = (const float*)d_in[4];
    const float* Wn  = (const float*)d_in[5];
    const float* bn  = (const float*)d_in[6];
    float* out = (float*)d_out;

    int N = in_sizes[0] / FN;
    int E = in_sizes[2] / FE;

    static int smem_set = 0;
    if (!smem_set) {
        cudaFuncSetAttribute(k_gemm1, cudaFuncAttributeMaxDynamicSharedMemorySize,
                             G1_SMEM);
        smem_set = 1;
    }

    int zb = (N * MSGW / 4 + 255) / 256;
    int wb = (128 * 192 + 255) / 256;
    k_prep<<<1 + zb + wb, 256>>>((const unsigned*)idx, We, Wn, E, N, zb);
    k_gemm1<<<(N + 63) / 64, 256, G1_SMEM>>>(nf, N);
    k_edges<<<(E + BE - 1) / BE, 256>>>(idx, ef, We, be, E);
    k_nodes<<<(N + 63) / 64, 256>>>(Wn, bn, out, N);
}